// round 3
// baseline (speedup 1.0000x reference)
#include <cuda_runtime.h>

// VecInt: scaling-and-squaring integration of a stationary velocity field.
// loc_shift [B=2, D=160, H=192, W=160, C=3] float32 (channels = dz,dy,dx).
//   disp = vel / 2^7;  repeat 7x:  disp = disp + warp(disp, disp)
// warp = trilinear sample of disp at (grid + disp), coords clipped to extent.

#define DB 2
#define DD 160
#define DH 192
#define DW 160
#define VOX (DD * DH * DW)        // 4,915,200
#define TOT (DB * VOX)            // 9,830,400
#define NTHREADS 256

// SoA ping-pong scratch: [2 buffers][3 channels][TOT].  2*3*TOT*4B = ~236 MB.
// (Rule: no cudaMalloc anywhere -> __device__ global scratch.)
__device__ float g_buf[2][3][TOT];

// One warp-and-add step:
//   self   = scale * src[v]
//   pos    = grid(v) + self               (clipped to [0, dim-1])
//   dst[v] = self + scale * trilinear(src, pos)
// IN_PACKED : src is the packed float3 harness input, else SoA scratch[in_sel]
// OUT_PACKED: dst is the packed float3 harness output, else SoA scratch[out_sel]
template <bool IN_PACKED, bool OUT_PACKED>
__global__ void __launch_bounds__(NTHREADS)
vecint_step(const float* __restrict__ inP, float* __restrict__ outP,
            int in_sel, int out_sel, float scale)
{
    const int tid = blockIdx.x * NTHREADS + threadIdx.x;  // grid is exact multiple
    // tid -> (b, z, y, x), x fastest (coalesced)
    const int x  = tid % DW;
    const int t1 = tid / DW;
    const int y  = t1 % DH;
    const int t2 = t1 / DH;
    const int z  = t2 % DD;
    const int b  = t2 / DD;
    const int base = b * VOX;

    const float* __restrict__ iz = g_buf[in_sel][0];
    const float* __restrict__ iy = g_buf[in_sel][1];
    const float* __restrict__ ix = g_buf[in_sel][2];
    float* __restrict__ oz = g_buf[out_sel][0];
    float* __restrict__ oy = g_buf[out_sel][1];
    float* __restrict__ ox = g_buf[out_sel][2];

    // --- own displacement (d0=dz, d1=dy, d2=dx), pre-scaled ---
    float d0, d1, d2;
    if (IN_PACKED) {
        const int p = tid * 3;
        d0 = __ldg(inP + p + 0);
        d1 = __ldg(inP + p + 1);
        d2 = __ldg(inP + p + 2);
    } else {
        d0 = __ldg(iz + tid);
        d1 = __ldg(iy + tid);
        d2 = __ldg(ix + tid);
    }
    d0 *= scale; d1 *= scale; d2 *= scale;

    // --- sample coords, clipped exactly like reference (clip -> floor) ---
    float pz = fminf(fmaxf((float)z + d0, 0.0f), (float)(DD - 1));
    float py = fminf(fmaxf((float)y + d1, 0.0f), (float)(DH - 1));
    float px = fminf(fmaxf((float)x + d2, 0.0f), (float)(DW - 1));

    const float fz0 = floorf(pz), fy0 = floorf(py), fx0 = floorf(px);
    const int z0 = (int)fz0, y0 = (int)fy0, x0 = (int)fx0;
    const int z1 = min(z0 + 1, DD - 1);
    const int y1 = min(y0 + 1, DH - 1);
    const int x1 = min(x0 + 1, DW - 1);

    const float dz = pz - fz0, dy = py - fy0, dx = px - fx0;
    const float wz = 1.0f - dz, wy = 1.0f - dy, wx = 1.0f - dx;

    const float w000 = wz * wy * wx;
    const float w001 = wz * wy * dx;
    const float w010 = wz * dy * wx;
    const float w011 = wz * dy * dx;
    const float w100 = dz * wy * wx;
    const float w101 = dz * wy * dx;
    const float w110 = dz * dy * wx;
    const float w111 = dz * dy * dx;

    const int i00 = base + (z0 * DH + y0) * DW;
    const int i01 = base + (z0 * DH + y1) * DW;
    const int i10 = base + (z1 * DH + y0) * DW;
    const int i11 = base + (z1 * DH + y1) * DW;

    float a0 = 0.0f, a1 = 0.0f, a2 = 0.0f;

    #define FETCH(IDX, W)                                           \
        do {                                                         \
            const int _i = (IDX);                                    \
            if (IN_PACKED) {                                         \
                const int _p = _i * 3;                               \
                a0 = fmaf((W), __ldg(inP + _p + 0), a0);             \
                a1 = fmaf((W), __ldg(inP + _p + 1), a1);             \
                a2 = fmaf((W), __ldg(inP + _p + 2), a2);             \
            } else {                                                 \
                a0 = fmaf((W), __ldg(iz + _i), a0);                  \
                a1 = fmaf((W), __ldg(iy + _i), a1);                  \
                a2 = fmaf((W), __ldg(ix + _i), a2);                  \
            }                                                        \
        } while (0)

    FETCH(i00 + x0, w000);
    FETCH(i00 + x1, w001);
    FETCH(i01 + x0, w010);
    FETCH(i01 + x1, w011);
    FETCH(i10 + x0, w100);
    FETCH(i10 + x1, w101);
    FETCH(i11 + x0, w110);
    FETCH(i11 + x1, w111);
    #undef FETCH

    const float o0 = fmaf(scale, a0, d0);
    const float o1 = fmaf(scale, a1, d1);
    const float o2 = fmaf(scale, a2, d2);

    if (OUT_PACKED) {
        const int p = tid * 3;
        outP[p + 0] = o0;
        outP[p + 1] = o1;
        outP[p + 2] = o2;
    } else {
        oz[tid] = o0;
        oy[tid] = o1;
        ox[tid] = o2;
    }
}

extern "C" void kernel_launch(void* const* d_in, const int* in_sizes, int n_in,
                              void* d_out, int out_size)
{
    const float* in  = (const float*)d_in[0];
    float*       out = (float*)d_out;

    const int nblocks = TOT / NTHREADS;   // 38,400 exactly
    const float inv = 1.0f / 128.0f;      // 2^-INT_STEPS (INT_STEPS = 7)

    // step 1 (scaling fused): packed input -> buf0
    vecint_step<true,  false><<<nblocks, NTHREADS>>>(in, nullptr, 0, 0, inv);
    // steps 2..6: ping-pong SoA scratch
    vecint_step<false, false><<<nblocks, NTHREADS>>>(nullptr, nullptr, 0, 1, 1.0f);
    vecint_step<false, false><<<nblocks, NTHREADS>>>(nullptr, nullptr, 1, 0, 1.0f);
    vecint_step<false, false><<<nblocks, NTHREADS>>>(nullptr, nullptr, 0, 1, 1.0f);
    vecint_step<false, false><<<nblocks, NTHREADS>>>(nullptr, nullptr, 1, 0, 1.0f);
    vecint_step<false, false><<<nblocks, NTHREADS>>>(nullptr, nullptr, 0, 1, 1.0f);
    // step 7: buf1 -> packed output
    vecint_step<false, true ><<<nblocks, NTHREADS>>>(nullptr, out, 1, 0, 1.0f);
}

// round 6
// speedup vs baseline: 1.0018x; 1.0018x over previous
#include <cuda_runtime.h>

// VecInt: scaling-and-squaring integration of a stationary velocity field.
// loc_shift [B=2, D=160, H=192, W=160, C=3] float32 (channels = dz,dy,dx).
//   disp = vel / 2^7;  repeat 7x:  disp = disp + warp(disp, disp)
// warp = trilinear sample of disp at (grid + disp), coords clipped to extent.
//
// ncu R3: L1tex=89.4% (binding), DRAM=27%. L1-issue/wavefront bound.
// This round: identical launch shell to the R3 passing kernel (1D grid,
// 256 threads), only the scratch layout changes to hybrid SoA:
// float2 plane (dz,dy) + float plane (dx). Corner gather = LDG.64+LDG.32
// (2 instrs) instead of 3x LDG.32  ->  per-thread mem instrs 30 -> 20.

#define DB 2
#define DD 160
#define DH 192
#define DW 160
#define VOX (DD * DH * DW)        // 4,915,200
#define TOT (DB * VOX)            // 9,830,400
#define NTHREADS 256

// Ping-pong scratch (no cudaMalloc allowed -> __device__ globals), ~236 MB.
__device__ float2 g_zy[2][TOT];   // (dz, dy) per voxel
__device__ float  g_xx[2][TOT];   // dx per voxel

// One warp-and-add step:
//   self   = scale * src[v]
//   pos    = grid(v) + self               (clipped to [0, dim-1])
//   dst[v] = self + scale * trilinear(src, pos)
// IN_PACKED : src is the packed float3 harness input, else scratch[in_sel]
// OUT_PACKED: dst is the packed float3 harness output, else scratch[out_sel]
template <bool IN_PACKED, bool OUT_PACKED>
__global__ void __launch_bounds__(NTHREADS)
vecint_step(const float* __restrict__ inP, float* __restrict__ outP,
            int in_sel, int out_sel, float scale)
{
    const int tid = blockIdx.x * NTHREADS + threadIdx.x;  // grid is exact multiple
    // tid -> (b, z, y, x), x fastest (coalesced)
    const int x  = tid % DW;
    const int t1 = tid / DW;
    const int y  = t1 % DH;
    const int t2 = t1 / DH;
    const int z  = t2 % DD;
    const int b  = t2 / DD;
    const int base = b * VOX;

    const float2* __restrict__ izy = g_zy[in_sel];
    const float*  __restrict__ ixx = g_xx[in_sel];

    // --- own displacement (d0=dz, d1=dy, d2=dx), pre-scaled ---
    float d0, d1, d2;
    if (IN_PACKED) {
        const int p = tid * 3;
        d0 = __ldg(inP + p + 0);
        d1 = __ldg(inP + p + 1);
        d2 = __ldg(inP + p + 2);
    } else {
        const float2 s = __ldg(izy + tid);
        d2 = __ldg(ixx + tid);
        d0 = s.x; d1 = s.y;
    }
    d0 *= scale; d1 *= scale; d2 *= scale;

    // --- sample coords, clipped exactly like reference (clip -> floor) ---
    float pz = fminf(fmaxf((float)z + d0, 0.0f), (float)(DD - 1));
    float py = fminf(fmaxf((float)y + d1, 0.0f), (float)(DH - 1));
    float px = fminf(fmaxf((float)x + d2, 0.0f), (float)(DW - 1));

    const float fz0 = floorf(pz), fy0 = floorf(py), fx0 = floorf(px);
    const int z0 = (int)fz0, y0 = (int)fy0, x0 = (int)fx0;
    const int z1 = min(z0 + 1, DD - 1);
    const int y1 = min(y0 + 1, DH - 1);
    const int x1 = min(x0 + 1, DW - 1);

    const float dz = pz - fz0, dy = py - fy0, dx = px - fx0;
    const float wz = 1.0f - dz, wy = 1.0f - dy, wx = 1.0f - dx;

    const float w000 = wz * wy * wx;
    const float w001 = wz * wy * dx;
    const float w010 = wz * dy * wx;
    const float w011 = wz * dy * dx;
    const float w100 = dz * wy * wx;
    const float w101 = dz * wy * dx;
    const float w110 = dz * dy * wx;
    const float w111 = dz * dy * dx;

    const int i00 = base + (z0 * DH + y0) * DW;
    const int i01 = base + (z0 * DH + y1) * DW;
    const int i10 = base + (z1 * DH + y0) * DW;
    const int i11 = base + (z1 * DH + y1) * DW;

    float a0 = 0.0f, a1 = 0.0f, a2 = 0.0f;

    #define FETCH(IDX, W)                                           \
        do {                                                         \
            const int _i = (IDX);                                    \
            if (IN_PACKED) {                                         \
                const int _p = _i * 3;                               \
                a0 = fmaf((W), __ldg(inP + _p + 0), a0);             \
                a1 = fmaf((W), __ldg(inP + _p + 1), a1);             \
                a2 = fmaf((W), __ldg(inP + _p + 2), a2);             \
            } else {                                                 \
                const float2 _c = __ldg(izy + _i);                   \
                const float  _f = __ldg(ixx + _i);                   \
                a0 = fmaf((W), _c.x, a0);                            \
                a1 = fmaf((W), _c.y, a1);                            \
                a2 = fmaf((W), _f, a2);                              \
            }                                                        \
        } while (0)

    FETCH(i00 + x0, w000);
    FETCH(i00 + x1, w001);
    FETCH(i01 + x0, w010);
    FETCH(i01 + x1, w011);
    FETCH(i10 + x0, w100);
    FETCH(i10 + x1, w101);
    FETCH(i11 + x0, w110);
    FETCH(i11 + x1, w111);
    #undef FETCH

    const float o0 = fmaf(scale, a0, d0);
    const float o1 = fmaf(scale, a1, d1);
    const float o2 = fmaf(scale, a2, d2);

    if (OUT_PACKED) {
        const int p = tid * 3;
        outP[p + 0] = o0;
        outP[p + 1] = o1;
        outP[p + 2] = o2;
    } else {
        g_zy[out_sel][tid] = make_float2(o0, o1);
        g_xx[out_sel][tid] = o2;
    }
}

extern "C" void kernel_launch(void* const* d_in, const int* in_sizes, int n_in,
                              void* d_out, int out_size)
{
    const float* in  = (const float*)d_in[0];
    float*       out = (float*)d_out;

    const int nblocks = TOT / NTHREADS;   // 38,400 exactly
    const float inv = 1.0f / 128.0f;      // 2^-INT_STEPS (INT_STEPS = 7)

    // step 1 (scaling fused): packed input -> buf0
    vecint_step<true,  false><<<nblocks, NTHREADS>>>(in, nullptr, 0, 0, inv);
    // steps 2..6: ping-pong hybrid-SoA scratch
    vecint_step<false, false><<<nblocks, NTHREADS>>>(nullptr, nullptr, 0, 1, 1.0f);
    vecint_step<false, false><<<nblocks, NTHREADS>>>(nullptr, nullptr, 1, 0, 1.0f);
    vecint_step<false, false><<<nblocks, NTHREADS>>>(nullptr, nullptr, 0, 1, 1.0f);
    vecint_step<false, false><<<nblocks, NTHREADS>>>(nullptr, nullptr, 1, 0, 1.0f);
    vecint_step<false, false><<<nblocks, NTHREADS>>>(nullptr, nullptr, 0, 1, 1.0f);
    // step 7: buf1 -> packed output
    vecint_step<false, true ><<<nblocks, NTHREADS>>>(nullptr, out, 1, 0, 1.0f);
}